// round 13
// baseline (speedup 1.0000x reference)
#include <cuda_runtime.h>
#include <cuda_bf16.h>
#include <math.h>
#include <stdint.h>

typedef __nv_bfloat16 bf16;

#define NTOK 16384
#define DD   1024
#define HH   4096
#define OO   1024
#define EE   8
#define NBANDS 4
#define NG   32
#define RR   16
#define MAXP2 36864
#define RTMAX2 (MAXP2/128)

// ---------------- device scratch ---------------------------------------------
__device__ int   g_e0[NTOK], g_e1[NTOK];
__device__ float g_g0[NTOK], g_g1[NTOK];
__device__ int   g_cntE[EE];
__device__ int   g_cntG[NG];
__device__ int   g_off[NG + 1];
__device__ int   g_cursor[NG];
__device__ int   g_pairTok[MAXP2];
__device__ float g_pairGate[MAXP2];
__device__ int   g_tokP[NTOK * 2];
__device__ bf16  g_r1h[MAXP2 * RR], g_r1l[MAXP2 * RR];
__device__ bf16  g_s2h[MAXP2 * RR], g_s2l[MAXP2 * RR];
__device__ bf16  g_xh[(size_t)NTOK * DD], g_xl[(size_t)NTOK * DD];
__device__ bf16  g_w1h[(size_t)EE * DD * HH], g_w1l[(size_t)EE * DD * HH];
__device__ bf16  g_w2h[(size_t)EE * HH * OO], g_w2l[(size_t)EE * HH * OO];
__device__ bf16  g_b1h[(size_t)NG * RR * HH], g_b1l[(size_t)NG * RR * HH];
__device__ bf16  g_b2h[(size_t)NG * RR * OO], g_b2l[(size_t)NG * RR * OO];
__device__ bf16  g_hh[(size_t)MAXP2 * HH], g_hl[(size_t)MAXP2 * HH];
__device__ float g_yp[(size_t)MAXP2 * OO];   // per-pair output (gathered later)

__device__ __forceinline__ float gelu_exact(float v) {
    return 0.5f * v * (1.0f + erff(v * 0.70710678118654752f));
}
__device__ __forceinline__ void split2(float v, bf16& h, bf16& l) {
    h = __float2bfloat16(v);
    l = __float2bfloat16(v - __bfloat162float(h));
}
__device__ __forceinline__ unsigned sm_u32(const void* p) {
    return (unsigned)__cvta_generic_to_shared(p);
}
__device__ __forceinline__ void cp16(void* d, const void* s, int sz) {
    asm volatile("cp.async.cg.shared.global [%0], [%1], 16, %2;\n"
                 :: "r"(sm_u32(d)), "l"(s), "r"(sz));
}
#define CP_COMMIT asm volatile("cp.async.commit_group;\n")
#define CP_WAIT0  asm volatile("cp.async.wait_group 0;\n" ::: "memory")
#define CP_WAIT1  asm volatile("cp.async.wait_group 1;\n" ::: "memory")
#define CP_WAIT2  asm volatile("cp.async.wait_group 2;\n" ::: "memory")

#define LDSM_X4(R0,R1,R2,R3,ADDR) \
    asm volatile("ldmatrix.sync.aligned.m8n8.x4.shared.b16 {%0,%1,%2,%3}, [%4];\n" \
                 : "=r"(R0),"=r"(R1),"=r"(R2),"=r"(R3) : "r"(ADDR))
#define LDSM_X4T(R0,R1,R2,R3,ADDR) \
    asm volatile("ldmatrix.sync.aligned.m8n8.x4.trans.shared.b16 {%0,%1,%2,%3}, [%4];\n" \
                 : "=r"(R0),"=r"(R1),"=r"(R2),"=r"(R3) : "r"(ADDR))
#define MMA16816(C,A,B) \
    asm volatile("mma.sync.aligned.m16n8k16.row.col.f32.bf16.bf16.f32 " \
                 "{%0,%1,%2,%3},{%4,%5,%6,%7},{%8,%9},{%0,%1,%2,%3};\n" \
                 : "+f"(C[0]),"+f"(C[1]),"+f"(C[2]),"+f"(C[3]) \
                 : "r"(A[0]),"r"(A[1]),"r"(A[2]),"r"(A[3]),"r"(B[0]),"r"(B[1]))

// dynamic smem: 3 stages of {Ah 10240 | Al 10240 | Bh 16896 | Bl 16896}
#define A_ST   40       // bf16 row stride for A (32 k + pad)
#define B_ST   264      // bf16 row stride for B (256 n + pad)
#define STG_AL 10240
#define STG_BH 20480
#define STG_BL 37376
#define STAGE_B 54272
#define NSTG   3
#define TOK_OFF  (STAGE_B * NSTG)        // 162816
#define GATE_OFF (TOK_OFF + 512)
#define SMEM_TOTAL (GATE_OFF + 512)      // 163840

// ---------------- init --------------------------------------------------------
__global__ void k_init(float* __restrict__ y, int out_size) {
    int i = blockIdx.x * 256 + threadIdx.x;
    if (i < out_size) y[i] = 0.f;
    if (i < EE) g_cntE[i] = 0;
    if (i < NG) g_cntG[i] = 0;
}

// ---------------- gating ------------------------------------------------------
__global__ void k_gate(const float* __restrict__ x, const float* __restrict__ wg,
                       const int* __restrict__ band) {
    int tok  = blockIdx.x * 4 + (threadIdx.x >> 5);
    int lane = threadIdx.x & 31;
    if (tok >= NTOK) return;
    const float* xr = x + (size_t)tok * DD;
    float acc[EE];
#pragma unroll
    for (int e = 0; e < EE; e++) acc[e] = 0.f;
    for (int d = lane; d < DD; d += 32) {
        float xv = xr[d];
        const float* w = wg + d * EE;
#pragma unroll
        for (int e = 0; e < EE; e++) acc[e] += xv * w[e];
    }
#pragma unroll
    for (int e = 0; e < EE; e++)
#pragma unroll
        for (int o = 16; o > 0; o >>= 1) acc[e] += __shfl_xor_sync(0xffffffffu, acc[e], o);
    if (lane == 0) {
        int e0 = 0; float v0 = acc[0];
#pragma unroll
        for (int e = 1; e < EE; e++) if (acc[e] > v0) { v0 = acc[e]; e0 = e; }
        int e1 = -1; float v1 = -INFINITY;
#pragma unroll
        for (int e = 0; e < EE; e++) if (e != e0 && acc[e] > v1) { v1 = acc[e]; e1 = e; }
        float z1 = expf(v1 - v0);
        float den = 1.0f + z1;
        g_e0[tok] = e0; g_e1[tok] = e1;
        g_g0[tok] = 1.0f / den; g_g1[tok] = z1 / den;
        int b = band[tok];
        atomicAdd(&g_cntE[e0], 1); atomicAdd(&g_cntE[e1], 1);
        atomicAdd(&g_cntG[e0 * NBANDS + b], 1);
        atomicAdd(&g_cntG[e1 * NBANDS + b], 1);
    }
}

// ---------------- loss --------------------------------------------------------
__global__ void k_loss(float* __restrict__ out, int out_size) {
    __shared__ float s[EE * 256];
    float acc[EE];
#pragma unroll
    for (int e = 0; e < EE; e++) acc[e] = 0.f;
    for (int t = threadIdx.x; t < NTOK; t += 256) {
        int e0 = g_e0[t], e1 = g_e1[t];
        float g0 = g_g0[t], g1 = g_g1[t];
#pragma unroll
        for (int e = 0; e < EE; e++)
            acc[e] += (e == e0 ? g0 : 0.f) + (e == e1 ? g1 : 0.f);
    }
#pragma unroll
    for (int e = 0; e < EE; e++) s[e * 256 + threadIdx.x] = acc[e];
    __syncthreads();
    for (int st = 128; st > 0; st >>= 1) {
        if (threadIdx.x < st)
#pragma unroll
            for (int e = 0; e < EE; e++)
                s[e * 256 + threadIdx.x] += s[e * 256 + threadIdx.x + st];
        __syncthreads();
    }
    if (threadIdx.x == 0) {
        float imp[EE], ld[EE];
#pragma unroll
        for (int e = 0; e < EE; e++) { imp[e] = s[e * 256]; ld[e] = (float)g_cntE[e]; }
        float m1 = 0.f, m2 = 0.f;
#pragma unroll
        for (int e = 0; e < EE; e++) { m1 += imp[e]; m2 += ld[e]; }
        m1 /= EE; m2 /= EE;
        float v1 = 0.f, v2 = 0.f;
#pragma unroll
        for (int e = 0; e < EE; e++) {
            float d1 = imp[e] - m1, d2 = ld[e] - m2;
            v1 += d1 * d1; v2 += d2 * d2;
        }
        v1 /= (EE - 1); v2 /= (EE - 1);
        out[out_size - 1] = 0.01f * (v1 / (m1 * m1 + 1e-10f) + v2 / (m2 * m2 + 1e-10f));
    }
}

// ---------------- prep + scatter ---------------------------------------------
__global__ void k_prep() {
    int i = blockIdx.x * 256 + threadIdx.x;
    if (i < MAXP2) { g_pairTok[i] = -1; g_pairGate[i] = 0.f; }
    if (i == 0) {
        int off = 0;
        for (int g = 0; g < NG; g++) {
            g_off[g] = off; g_cursor[g] = off;
            off += ((g_cntG[g] + 127) >> 7) << 7;
        }
        g_off[NG] = off;
    }
}

__global__ void k_scatter(const int* __restrict__ band) {
    int t = blockIdx.x * 256 + threadIdx.x;
    if (t >= NTOK) return;
    int b = band[t];
    int grp0 = g_e0[t] * NBANDS + b;
    int p0 = atomicAdd(&g_cursor[grp0], 1);
    g_pairTok[p0] = t; g_pairGate[p0] = g_g0[t];
    int grp1 = g_e1[t] * NBANDS + b;
    int p1 = atomicAdd(&g_cursor[grp1], 1);
    g_pairTok[p1] = t; g_pairGate[p1] = g_g1[t];
    g_tokP[t * 2] = p0; g_tokP[t * 2 + 1] = p1;
}

// ---------------- fp32 -> bf16 hi/lo split kernels ---------------------------
__device__ __forceinline__ void split_body(const float* __restrict__ src,
                                           bf16* __restrict__ hi, bf16* __restrict__ lo,
                                           int n4) {
    int i = blockIdx.x * 256 + threadIdx.x;
    if (i >= n4) return;
    float4 v = ((const float4*)src)[i];
    bf16 h0, h1, h2, h3, l0, l1, l2, l3;
    split2(v.x, h0, l0); split2(v.y, h1, l1);
    split2(v.z, h2, l2); split2(v.w, h3, l3);
    ((__nv_bfloat162*)hi)[i * 2 + 0] = __halves2bfloat162(h0, h1);
    ((__nv_bfloat162*)hi)[i * 2 + 1] = __halves2bfloat162(h2, h3);
    ((__nv_bfloat162*)lo)[i * 2 + 0] = __halves2bfloat162(l0, l1);
    ((__nv_bfloat162*)lo)[i * 2 + 1] = __halves2bfloat162(l2, l3);
}
__global__ void k_split_x (const float* s) { split_body(s, g_xh,  g_xl,  NTOK * DD / 4); }
__global__ void k_split_w1(const float* s) { split_body(s, g_w1h, g_w1l, EE * DD * HH / 4); }
__global__ void k_split_w2(const float* s) { split_body(s, g_w2h, g_w2l, EE * HH * OO / 4); }
__global__ void k_split_b1(const float* s) { split_body(s, g_b1h, g_b1l, NG * RR * HH / 4); }
__global__ void k_split_b2(const float* s) { split_body(s, g_b2h, g_b2l, NG * RR * OO / 4); }

// ---------------- group id ----------------------------------------------------
__device__ __forceinline__ int grp_of(int row0) {
    int grp = 0;
#pragma unroll
    for (int i = 1; i < NG; i++) if (row0 >= g_off[i]) grp = i;
    return grp;
}

// ---------------- r1 = 2*(x . A1[grp]) ---------------------------------------
__global__ void __launch_bounds__(256) k_r1(const float* __restrict__ x,
                                            const float* __restrict__ A1) {
    __shared__ float sA[32][RR];
    int row0 = blockIdx.x * 128;
    int grp  = grp_of(row0);
    int tid  = threadIdx.x;
    int row  = tid >> 1, half = tid & 1;
    int tok  = g_pairTok[row0 + row];
    const float* A = A1 + (size_t)grp * DD * RR;
    float acc[8];
#pragma unroll
    for (int q = 0; q < 8; q++) acc[q] = 0.f;
    for (int k0 = 0; k0 < DD; k0 += 32) {
        int kk = tid >> 3, rp = tid & 7;
        *(float2*)&sA[kk][rp * 2] = *(const float2*)(A + (size_t)(k0 + kk) * RR + rp * 2);
        __syncthreads();
        if (tok >= 0) {
            const float* xr = x + (size_t)tok * DD + k0;
#pragma unroll
            for (int k = 0; k < 32; k++) {
                float xv = xr[k];
                float4 a0 = *(const float4*)&sA[k][half * 8];
                float4 a1 = *(const float4*)&sA[k][half * 8 + 4];
                acc[0] += xv * a0.x; acc[1] += xv * a0.y;
                acc[2] += xv * a0.z; acc[3] += xv * a0.w;
                acc[4] += xv * a1.x; acc[5] += xv * a1.y;
                acc[6] += xv * a1.z; acc[7] += xv * a1.w;
            }
        }
        __syncthreads();
    }
#pragma unroll
    for (int q = 0; q < 8; q++) {
        bf16 h, l; split2(2.0f * acc[q], h, l);
        size_t o = (size_t)(row0 + row) * RR + half * 8 + q;
        g_r1h[o] = h; g_r1l[o] = l;
    }
}

// ---------------- s2 = 2*(h . A2[grp]) ---------------------------------------
__global__ void __launch_bounds__(256) k_s2(const float* __restrict__ A2) {
    __shared__ float sA[32][RR];
    int row0 = blockIdx.x * 128;
    int grp  = grp_of(row0);
    int tid  = threadIdx.x;
    int row  = tid >> 1, half = tid & 1;
    const float* A = A2 + (size_t)grp * HH * RR;
    const __nv_bfloat162* hh = (const __nv_bfloat162*)(g_hh + (size_t)(row0 + row) * HH);
    const __nv_bfloat162* hl = (const __nv_bfloat162*)(g_hl + (size_t)(row0 + row) * HH);
    float acc[8];
#pragma unroll
    for (int q = 0; q < 8; q++) acc[q] = 0.f;
    for (int k0 = 0; k0 < HH; k0 += 32) {
        int kk = tid >> 3, rp = tid & 7;
        *(float2*)&sA[kk][rp * 2] = *(const float2*)(A + (size_t)(k0 + kk) * RR + rp * 2);
        __syncthreads();
#pragma unroll
        for (int k2 = 0; k2 < 16; k2++) {
            __nv_bfloat162 vh = hh[k0 / 2 + k2];
            __nv_bfloat162 vl = hl[k0 / 2 + k2];
            float hv0 = __bfloat162float(vh.x) + __bfloat162float(vl.x);
            float hv1 = __bfloat162float(vh.y) + __bfloat162float(vl.y);
#pragma unroll
            for (int pair = 0; pair < 2; pair++) {
                float xv = pair ? hv1 : hv0;
                int k = k2 * 2 + pair;
                float4 a0 = *(const float4*)&sA[k][half * 8];
                float4 a1 = *(const float4*)&sA[k][half * 8 + 4];
                acc[0] += xv * a0.x; acc[1] += xv * a0.y;
                acc[2] += xv * a0.z; acc[3] += xv * a0.w;
                acc[4] += xv * a1.x; acc[5] += xv * a1.y;
                acc[6] += xv * a1.z; acc[7] += xv * a1.w;
            }
        }
        __syncthreads();
    }
#pragma unroll
    for (int q = 0; q < 8; q++) {
        bf16 h, l; split2(2.0f * acc[q], h, l);
        size_t o = (size_t)(row0 + row) * RR + half * 8 + q;
        g_s2h[o] = h; g_s2l[o] = l;
    }
}

// ---------------- GEMM: 128x256 CTA tile, warp 64x64, 3-stage, 3-term --------
template<int KD, int ND, bool MLP1>
__global__ void __launch_bounds__(256, 1) k_gemm(const float* __restrict__ bias_g) {
    extern __shared__ char smem[];
    int*   sTok  = (int*)(smem + TOK_OFF);
    float* sGate = (float*)(smem + GATE_OFF);

    int row0 = blockIdx.y * 128;
    if (row0 >= g_off[NG]) return;
    int grp = grp_of(row0);
    int e  = grp >> 2;
    int j0 = blockIdx.x * 256;
    int tid = threadIdx.x;

    if (tid < 128) {
        sTok[tid]  = g_pairTok[row0 + tid];
        sGate[tid] = g_pairGate[row0 + tid];
    }
    __syncthreads();

    const bf16* Ah = MLP1 ? g_xh  : g_hh;
    const bf16* Al = MLP1 ? g_xl  : g_hl;
    const bf16* Wh = MLP1 ? g_w1h : g_w2h;
    const bf16* Wl = MLP1 ? g_w1l : g_w2l;
    const bf16* Rh = MLP1 ? g_r1h : g_s2h;
    const bf16* Rl = MLP1 ? g_r1l : g_s2l;
    const bf16* Lh = MLP1 ? g_b1h : g_b2h;
    const bf16* Ll = MLP1 ? g_b1l : g_b2l;

    const int SM32 = KD / 32;
    const int S    = SM32 + 1;    // + LoRA (K=16) stage

    auto fill = [&](int s) {
        char* base = smem + (s % NSTG) * STAGE_B;
        bf16* dAh = (bf16*)base;
        bf16* dAl = (bf16*)(base + STG_AL);
        bf16* dBh = (bf16*)(base + STG_BH);
        bf16* dBl = (bf16*)(base + STG_BL);
        int r = tid >> 1;
        if (s < SM32) {
            int k0 = s * 32;
            size_t aoff; int sz = 16;
            if (MLP1) {
                int tok = sTok[r];
                sz = tok >= 0 ? 16 : 0;
                aoff = (size_t)(tok >= 0 ? tok : 0) * KD + k0;
            } else aoff = (size_t)(row0 + r) * KD + k0;
#pragma unroll
            for (int q = 0; q < 2; q++) {
                int c = (tid & 1) * 2 + q;        // 0..3 (32 bf16 per row)
                cp16(dAh + r * A_ST + c * 8, Ah + aoff + c * 8, sz);
                cp16(dAl + r * A_ST + c * 8, Al + aoff + c * 8, sz);
            }
            int br = tid >> 3;                    // 0..31 (k row)
            size_t woff = (size_t)e * ((size_t)KD * ND) + (size_t)(k0 + br) * ND + j0;
#pragma unroll
            for (int q = 0; q < 4; q++) {
                int c = (tid & 7) + q * 8;        // 0..31 (col chunks of 8)
                cp16(dBh + br * B_ST + c * 8, Wh + woff + c * 8, 16);
                cp16(dBl + br * B_ST + c * 8, Wl + woff + c * 8, 16);
            }
        } else {
            // LoRA: A 128x16, B 16x256
            int seg = tid & 1;
            size_t roff = (size_t)(row0 + r) * RR + seg * 8;
            cp16(dAh + r * A_ST + seg * 8, Rh + roff, 16);
            cp16(dAl + r * A_ST + seg * 8, Rl + roff, 16);
            int br = tid >> 4;                    // 0..15
            size_t boff = ((size_t)grp * RR + br) * ND + j0;
#pragma unroll
            for (int q = 0; q < 2; q++) {
                int c = (tid & 15) + q * 16;      // 0..31
                cp16(dBh + br * B_ST + c * 8, Lh + boff + c * 8, 16);
                cp16(dBl + br * B_ST + c * 8, Ll + boff + c * 8, 16);
            }
        }
        CP_COMMIT;
    };

    const int warp = tid >> 5, lane = tid & 31;
    const int wm = (warp >> 2) * 64, wn = (warp & 3) * 64;
    const int arow = lane & 15, acol = (lane >> 4) * 8;
    const int bg = lane >> 3;
    const int brow = (bg & 1) * 8 + (lane & 7);

    float acc[4][8][4];
#pragma unroll
    for (int mt = 0; mt < 4; mt++)
#pragma unroll
        for (int nt = 0; nt < 8; nt++)
#pragma unroll
            for (int q = 0; q < 4; q++) acc[mt][nt][q] = 0.f;

    fill(0);
    if (S > 1) fill(1);

    for (int s = 0; s < S; s++) {
        if (s + 2 < S) { fill(s + 2); CP_WAIT2; }
        else if (s + 1 < S) { CP_WAIT1; }
        else { CP_WAIT0; }
        __syncthreads();

        char* base = smem + (s % NSTG) * STAGE_B;
        bf16* bAh = (bf16*)base;
        bf16* bAl = (bf16*)(base + STG_AL);
        bf16* bBh = (bf16*)(base + STG_BH);
        bf16* bBl = (bf16*)(base + STG_BL);
        int nh = (s == SM32) ? 1 : 2;

        for (int kh = 0; kh < nh; kh++) {
            unsigned ah[4][4], al[4][4];
#pragma unroll
            for (int mt = 0; mt < 4; mt++) {
                unsigned ad = sm_u32(bAh + (wm + mt * 16 + arow) * A_ST + kh * 16 + acol);
                LDSM_X4(ah[mt][0], ah[mt][1], ah[mt][2], ah[mt][3], ad);
                unsigned ad2 = sm_u32(bAl + (wm + mt * 16 + arow) * A_ST + kh * 16 + acol);
                LDSM_X4(al[mt][0], al[mt][1], al[mt][2], al[mt][3], ad2);
            }
#pragma unroll
            for (int np = 0; np < 4; np++) {
                unsigned bh[2][2], bl[2][2];
                int bcol = wn + np * 16 + (bg >> 1) * 8;
                unsigned bd = sm_u32(bBh + (kh * 16 + brow) * B_ST + bcol);
                LDSM_X4T(bh[0][0], bh[0][1], bh[1][0], bh[1][1], bd);
                unsigned bd2 = sm_u32(bBl + (kh * 16 + brow) * B_ST + bcol);
                LDSM_X4T(bl[0][0], bl[0][1], bl[1][0], bl[1][1], bd2);
#pragma unroll
                for (int mt = 0; mt < 4; mt++) {
                    MMA16816(acc[mt][np * 2 + 0], ah[mt], bh[0]);
                    MMA16816(acc[mt][np * 2 + 1], ah[mt], bh[1]);
                }
#pragma unroll
                for (int mt = 0; mt < 4; mt++) {
                    MMA16816(acc[mt][np * 2 + 0], ah[mt], bl[0]);
                    MMA16816(acc[mt][np * 2 + 1], ah[mt], bl[1]);
                }
#pragma unroll
                for (int mt = 0; mt < 4; mt++) {
                    MMA16816(acc[mt][np * 2 + 0], al[mt], bh[0]);
                    MMA16816(acc[mt][np * 2 + 1], al[mt], bh[1]);
                }
            }
        }
        __syncthreads();
    }

    // epilogue
#pragma unroll
    for (int mt = 0; mt < 4; mt++) {
#pragma unroll
        for (int nt = 0; nt < 8; nt++) {
            int c0  = wn + nt * 8 + (lane & 3) * 2;
            int col = j0 + c0;
            float bias0 = bias_g[(size_t)e * ND + col];
            float bias1 = bias_g[(size_t)e * ND + col + 1];
#pragma unroll
            for (int hf = 0; hf < 2; hf++) {
                int r = wm + mt * 16 + (lane >> 2) + hf * 8;
                float v0 = acc[mt][nt][hf * 2 + 0] + bias0;
                float v1 = acc[mt][nt][hf * 2 + 1] + bias1;
                if (MLP1) {
                    v0 = gelu_exact(v0); v1 = gelu_exact(v1);
                    bf16 h0, l0, h1, l1;
                    split2(v0, h0, l0); split2(v1, h1, l1);
                    size_t o = (size_t)(row0 + r) * ND + col;
                    *(__nv_bfloat162*)(g_hh + o) = __halves2bfloat162(h0, h1);
                    *(__nv_bfloat162*)(g_hl + o) = __halves2bfloat162(l0, l1);
                } else {
                    float gv = sGate[r];
                    size_t o = (size_t)(row0 + r) * ND + col;
                    g_yp[o]     = gv * v0;
                    g_yp[o + 1] = gv * v1;
                }
            }
        }
    }
}

// ---------------- gather: y[tok] = yp[p0] + yp[p1] ---------------------------
__global__ void k_gather(float* __restrict__ y) {
    int idx = blockIdx.x * 256 + threadIdx.x;
    if (idx >= NTOK * (OO / 4)) return;
    int tok = idx / (OO / 4);
    int c4  = idx - tok * (OO / 4);
    int p0 = g_tokP[tok * 2], p1 = g_tokP[tok * 2 + 1];
    float4 a = ((const float4*)g_yp)[(size_t)p0 * (OO / 4) + c4];
    float4 b = ((const float4*)g_yp)[(size_t)p1 * (OO / 4) + c4];
    float4 r;
    r.x = a.x + b.x; r.y = a.y + b.y; r.z = a.z + b.z; r.w = a.w + b.w;
    ((float4*)y)[idx] = r;
}

// ---------------- launch ------------------------------------------------------
extern "C" void kernel_launch(void* const* d_in, const int* in_sizes, int n_in,
                              void* d_out, int out_size) {
    const float* x    = (const float*)d_in[0];
    const int*   band = (const int*)d_in[1];
    const float* wg   = (const float*)d_in[2];
    const float* W1   = (const float*)d_in[3];
    const float* b1   = (const float*)d_in[4];
    const float* W2   = (const float*)d_in[5];
    const float* b2   = (const float*)d_in[6];
    const float* A1   = (const float*)d_in[7];
    const float* B1   = (const float*)d_in[8];
    const float* A2   = (const float*)d_in[9];
    const float* B2   = (const float*)d_in[10];
    float* out = (float*)d_out;

    cudaFuncSetAttribute(k_gemm<DD, HH, true >,
                         cudaFuncAttributeMaxDynamicSharedMemorySize, SMEM_TOTAL);
    cudaFuncSetAttribute(k_gemm<HH, OO, false>,
                         cudaFuncAttributeMaxDynamicSharedMemorySize, SMEM_TOTAL);

    k_init<<<(out_size + 255) / 256, 256>>>(out, out_size);
    k_gate<<<NTOK / 4, 128>>>(x, wg, band);
    k_loss<<<1, 256>>>(out, out_size);
    k_prep<<<(MAXP2 + 255) / 256, 256>>>();
    k_scatter<<<NTOK / 256, 256>>>(band);

    k_split_x <<<(NTOK * DD / 4 + 255) / 256, 256>>>(x);
    k_split_w1<<<(EE * DD * HH / 4 + 255) / 256, 256>>>(W1);
    k_split_w2<<<(EE * HH * OO / 4 + 255) / 256, 256>>>(W2);
    k_split_b1<<<(NG * RR * HH / 4 + 255) / 256, 256>>>(B1);
    k_split_b2<<<(NG * RR * OO / 4 + 255) / 256, 256>>>(B2);

    k_r1<<<RTMAX2, 256>>>(x, A1);
    k_gemm<DD, HH, true ><<<dim3(HH / 256, RTMAX2), 256, SMEM_TOTAL>>>(b1);
    k_s2<<<RTMAX2, 256>>>(A2);
    k_gemm<HH, OO, false><<<dim3(OO / 256, RTMAX2), 256, SMEM_TOTAL>>>(b2);
    k_gather<<<(NTOK * (OO / 4) + 255) / 256, 256>>>(out);
}

// round 14
// speedup vs baseline: 1.0300x; 1.0300x over previous
#include <cuda_runtime.h>
#include <cuda_bf16.h>
#include <math.h>
#include <stdint.h>

typedef __nv_bfloat16 bf16;

#define NTOK 16384
#define DD   1024
#define HH   4096
#define OO   1024
#define EE   8
#define NBANDS 4
#define NG   32
#define RR   16
#define MAXP2 36864
#define RTMAX2 (MAXP2/128)

// ---------------- device scratch ---------------------------------------------
__device__ int   g_e0[NTOK], g_e1[NTOK];
__device__ float g_g0[NTOK], g_g1[NTOK];
__device__ int   g_cntE[EE];
__device__ int   g_cntG[NG];
__device__ int   g_off[NG + 1];
__device__ int   g_cursor[NG];
__device__ int   g_pairTok[MAXP2];
__device__ float g_pairGate[MAXP2];
__device__ int   g_tokP[NTOK * 2];
__device__ bf16  g_r1h[MAXP2 * RR], g_r1l[MAXP2 * RR];
__device__ bf16  g_s2h[MAXP2 * RR], g_s2l[MAXP2 * RR];
__device__ bf16  g_xh[(size_t)NTOK * DD], g_xl[(size_t)NTOK * DD];
__device__ bf16  g_w1h[(size_t)EE * DD * HH], g_w1l[(size_t)EE * DD * HH];
__device__ bf16  g_w2h[(size_t)EE * HH * OO], g_w2l[(size_t)EE * HH * OO];
__device__ bf16  g_b1h[(size_t)NG * RR * HH], g_b1l[(size_t)NG * RR * HH];
__device__ bf16  g_b2h[(size_t)NG * RR * OO], g_b2l[(size_t)NG * RR * OO];
__device__ bf16  g_hh[(size_t)MAXP2 * HH], g_hl[(size_t)MAXP2 * HH];
__device__ float g_yp[(size_t)MAXP2 * OO];   // per-pair output (gathered later)

__device__ __forceinline__ float gelu_exact(float v) {
    return 0.5f * v * (1.0f + erff(v * 0.70710678118654752f));
}
__device__ __forceinline__ void split2(float v, bf16& h, bf16& l) {
    h = __float2bfloat16(v);
    l = __float2bfloat16(v - __bfloat162float(h));
}
__device__ __forceinline__ unsigned sm_u32(const void* p) {
    return (unsigned)__cvta_generic_to_shared(p);
}
__device__ __forceinline__ void cp16(void* d, const void* s, int sz) {
    asm volatile("cp.async.cg.shared.global [%0], [%1], 16, %2;\n"
                 :: "r"(sm_u32(d)), "l"(s), "r"(sz));
}
#define CP_COMMIT asm volatile("cp.async.commit_group;\n")
#define CP_WAIT0  asm volatile("cp.async.wait_group 0;\n" ::: "memory")
#define CP_WAIT1  asm volatile("cp.async.wait_group 1;\n" ::: "memory")
#define CP_WAIT2  asm volatile("cp.async.wait_group 2;\n" ::: "memory")

#define LDSM_X4(R0,R1,R2,R3,ADDR) \
    asm volatile("ldmatrix.sync.aligned.m8n8.x4.shared.b16 {%0,%1,%2,%3}, [%4];\n" \
                 : "=r"(R0),"=r"(R1),"=r"(R2),"=r"(R3) : "r"(ADDR))
#define LDSM_X4T(R0,R1,R2,R3,ADDR) \
    asm volatile("ldmatrix.sync.aligned.m8n8.x4.trans.shared.b16 {%0,%1,%2,%3}, [%4];\n" \
                 : "=r"(R0),"=r"(R1),"=r"(R2),"=r"(R3) : "r"(ADDR))
#define MMA16816(C,A,B) \
    asm volatile("mma.sync.aligned.m16n8k16.row.col.f32.bf16.bf16.f32 " \
                 "{%0,%1,%2,%3},{%4,%5,%6,%7},{%8,%9},{%0,%1,%2,%3};\n" \
                 : "+f"(C[0]),"+f"(C[1]),"+f"(C[2]),"+f"(C[3]) \
                 : "r"(A[0]),"r"(A[1]),"r"(A[2]),"r"(A[3]),"r"(B[0]),"r"(B[1]))

// dynamic smem: 3 stages of {Ah 10240 | Al 10240 | Bh 8704 | Bl 8704} = 37888 B
#define A_ST   40       // bf16 row stride for A (32 k + pad)
#define B_ST   136      // bf16 row stride for B (128 n + pad)
#define STG_AL 10240
#define STG_BH 20480
#define STG_BL 29184
#define STAGE_B 37888
#define NSTG   3
#define TOK_OFF  (STAGE_B * NSTG)        // 113664
#define GATE_OFF (TOK_OFF + 512)
#define SMEM_TOTAL (GATE_OFF + 512)      // 114688

// ---------------- init --------------------------------------------------------
__global__ void k_init(float* __restrict__ y, int out_size) {
    int i = blockIdx.x * 256 + threadIdx.x;
    if (i < out_size) y[i] = 0.f;
    if (i < EE) g_cntE[i] = 0;
    if (i < NG) g_cntG[i] = 0;
}

// ---------------- gating ------------------------------------------------------
__global__ void k_gate(const float* __restrict__ x, const float* __restrict__ wg,
                       const int* __restrict__ band) {
    int tok  = blockIdx.x * 4 + (threadIdx.x >> 5);
    int lane = threadIdx.x & 31;
    if (tok >= NTOK) return;
    const float* xr = x + (size_t)tok * DD;
    float acc[EE];
#pragma unroll
    for (int e = 0; e < EE; e++) acc[e] = 0.f;
    for (int d = lane; d < DD; d += 32) {
        float xv = xr[d];
        const float* w = wg + d * EE;
#pragma unroll
        for (int e = 0; e < EE; e++) acc[e] += xv * w[e];
    }
#pragma unroll
    for (int e = 0; e < EE; e++)
#pragma unroll
        for (int o = 16; o > 0; o >>= 1) acc[e] += __shfl_xor_sync(0xffffffffu, acc[e], o);
    if (lane == 0) {
        int e0 = 0; float v0 = acc[0];
#pragma unroll
        for (int e = 1; e < EE; e++) if (acc[e] > v0) { v0 = acc[e]; e0 = e; }
        int e1 = -1; float v1 = -INFINITY;
#pragma unroll
        for (int e = 0; e < EE; e++) if (e != e0 && acc[e] > v1) { v1 = acc[e]; e1 = e; }
        float z1 = expf(v1 - v0);
        float den = 1.0f + z1;
        g_e0[tok] = e0; g_e1[tok] = e1;
        g_g0[tok] = 1.0f / den; g_g1[tok] = z1 / den;
        int b = band[tok];
        atomicAdd(&g_cntE[e0], 1); atomicAdd(&g_cntE[e1], 1);
        atomicAdd(&g_cntG[e0 * NBANDS + b], 1);
        atomicAdd(&g_cntG[e1 * NBANDS + b], 1);
    }
}

// ---------------- loss --------------------------------------------------------
__global__ void k_loss(float* __restrict__ out, int out_size) {
    __shared__ float s[EE * 256];
    float acc[EE];
#pragma unroll
    for (int e = 0; e < EE; e++) acc[e] = 0.f;
    for (int t = threadIdx.x; t < NTOK; t += 256) {
        int e0 = g_e0[t], e1 = g_e1[t];
        float g0 = g_g0[t], g1 = g_g1[t];
#pragma unroll
        for (int e = 0; e < EE; e++)
            acc[e] += (e == e0 ? g0 : 0.f) + (e == e1 ? g1 : 0.f);
    }
#pragma unroll
    for (int e = 0; e < EE; e++) s[e * 256 + threadIdx.x] = acc[e];
    __syncthreads();
    for (int st = 128; st > 0; st >>= 1) {
        if (threadIdx.x < st)
#pragma unroll
            for (int e = 0; e < EE; e++)
                s[e * 256 + threadIdx.x] += s[e * 256 + threadIdx.x + st];
        __syncthreads();
    }
    if (threadIdx.x == 0) {
        float imp[EE], ld[EE];
#pragma unroll
        for (int e = 0; e < EE; e++) { imp[e] = s[e * 256]; ld[e] = (float)g_cntE[e]; }
        float m1 = 0.f, m2 = 0.f;
#pragma unroll
        for (int e = 0; e < EE; e++) { m1 += imp[e]; m2 += ld[e]; }
        m1 /= EE; m2 /= EE;
        float v1 = 0.f, v2 = 0.f;
#pragma unroll
        for (int e = 0; e < EE; e++) {
            float d1 = imp[e] - m1, d2 = ld[e] - m2;
            v1 += d1 * d1; v2 += d2 * d2;
        }
        v1 /= (EE - 1); v2 /= (EE - 1);
        out[out_size - 1] = 0.01f * (v1 / (m1 * m1 + 1e-10f) + v2 / (m2 * m2 + 1e-10f));
    }
}

// ---------------- prep + scatter ---------------------------------------------
__global__ void k_prep() {
    int i = blockIdx.x * 256 + threadIdx.x;
    if (i < MAXP2) { g_pairTok[i] = -1; g_pairGate[i] = 0.f; }
    if (i == 0) {
        int off = 0;
        for (int g = 0; g < NG; g++) {
            g_off[g] = off; g_cursor[g] = off;
            off += ((g_cntG[g] + 127) >> 7) << 7;
        }
        g_off[NG] = off;
    }
}

__global__ void k_scatter(const int* __restrict__ band) {
    int t = blockIdx.x * 256 + threadIdx.x;
    if (t >= NTOK) return;
    int b = band[t];
    int grp0 = g_e0[t] * NBANDS + b;
    int p0 = atomicAdd(&g_cursor[grp0], 1);
    g_pairTok[p0] = t; g_pairGate[p0] = g_g0[t];
    int grp1 = g_e1[t] * NBANDS + b;
    int p1 = atomicAdd(&g_cursor[grp1], 1);
    g_pairTok[p1] = t; g_pairGate[p1] = g_g1[t];
    g_tokP[t * 2] = p0; g_tokP[t * 2 + 1] = p1;
}

// ---------------- fp32 -> bf16 hi/lo split kernels ---------------------------
__device__ __forceinline__ void split_body(const float* __restrict__ src,
                                           bf16* __restrict__ hi, bf16* __restrict__ lo,
                                           int n4) {
    int i = blockIdx.x * 256 + threadIdx.x;
    if (i >= n4) return;
    float4 v = ((const float4*)src)[i];
    bf16 h0, h1, h2, h3, l0, l1, l2, l3;
    split2(v.x, h0, l0); split2(v.y, h1, l1);
    split2(v.z, h2, l2); split2(v.w, h3, l3);
    ((__nv_bfloat162*)hi)[i * 2 + 0] = __halves2bfloat162(h0, h1);
    ((__nv_bfloat162*)hi)[i * 2 + 1] = __halves2bfloat162(h2, h3);
    ((__nv_bfloat162*)lo)[i * 2 + 0] = __halves2bfloat162(l0, l1);
    ((__nv_bfloat162*)lo)[i * 2 + 1] = __halves2bfloat162(l2, l3);
}
__global__ void k_split_x (const float* s) { split_body(s, g_xh,  g_xl,  NTOK * DD / 4); }
__global__ void k_split_w1(const float* s) { split_body(s, g_w1h, g_w1l, EE * DD * HH / 4); }
__global__ void k_split_w2(const float* s) { split_body(s, g_w2h, g_w2l, EE * HH * OO / 4); }
__global__ void k_split_b1(const float* s) { split_body(s, g_b1h, g_b1l, NG * RR * HH / 4); }
__global__ void k_split_b2(const float* s) { split_body(s, g_b2h, g_b2l, NG * RR * OO / 4); }

// ---------------- group id ----------------------------------------------------
__device__ __forceinline__ int grp_of(int row0) {
    int grp = 0;
#pragma unroll
    for (int i = 1; i < NG; i++) if (row0 >= g_off[i]) grp = i;
    return grp;
}

// ---------------- r1 = 2*(x . A1[grp]) ---------------------------------------
__global__ void __launch_bounds__(256) k_r1(const float* __restrict__ x,
                                            const float* __restrict__ A1) {
    __shared__ float sA[32][RR];
    int row0 = blockIdx.x * 128;
    int grp  = grp_of(row0);
    int tid  = threadIdx.x;
    int row  = tid >> 1, half = tid & 1;
    int tok  = g_pairTok[row0 + row];
    const float* A = A1 + (size_t)grp * DD * RR;
    float acc[8];
#pragma unroll
    for (int q = 0; q < 8; q++) acc[q] = 0.f;
    for (int k0 = 0; k0 < DD; k0 += 32) {
        int kk = tid >> 3, rp = tid & 7;
        *(float2*)&sA[kk][rp * 2] = *(const float2*)(A + (size_t)(k0 + kk) * RR + rp * 2);
        __syncthreads();
        if (tok >= 0) {
            const float* xr = x + (size_t)tok * DD + k0;
#pragma unroll
            for (int k = 0; k < 32; k++) {
                float xv = xr[k];
                float4 a0 = *(const float4*)&sA[k][half * 8];
                float4 a1 = *(const float4*)&sA[k][half * 8 + 4];
                acc[0] += xv * a0.x; acc[1] += xv * a0.y;
                acc[2] += xv * a0.z; acc[3] += xv * a0.w;
                acc[4] += xv * a1.x; acc[5] += xv * a1.y;
                acc[6] += xv * a1.z; acc[7] += xv * a1.w;
            }
        }
        __syncthreads();
    }
#pragma unroll
    for (int q = 0; q < 8; q++) {
        bf16 h, l; split2(2.0f * acc[q], h, l);
        size_t o = (size_t)(row0 + row) * RR + half * 8 + q;
        g_r1h[o] = h; g_r1l[o] = l;
    }
}

// ---------------- s2 = 2*(h . A2[grp]) ---------------------------------------
__global__ void __launch_bounds__(256) k_s2(const float* __restrict__ A2) {
    __shared__ float sA[32][RR];
    int row0 = blockIdx.x * 128;
    int grp  = grp_of(row0);
    int tid  = threadIdx.x;
    int row  = tid >> 1, half = tid & 1;
    const float* A = A2 + (size_t)grp * HH * RR;
    const __nv_bfloat162* hh = (const __nv_bfloat162*)(g_hh + (size_t)(row0 + row) * HH);
    const __nv_bfloat162* hl = (const __nv_bfloat162*)(g_hl + (size_t)(row0 + row) * HH);
    float acc[8];
#pragma unroll
    for (int q = 0; q < 8; q++) acc[q] = 0.f;
    for (int k0 = 0; k0 < HH; k0 += 32) {
        int kk = tid >> 3, rp = tid & 7;
        *(float2*)&sA[kk][rp * 2] = *(const float2*)(A + (size_t)(k0 + kk) * RR + rp * 2);
        __syncthreads();
#pragma unroll
        for (int k2 = 0; k2 < 16; k2++) {
            __nv_bfloat162 vh = hh[k0 / 2 + k2];
            __nv_bfloat162 vl = hl[k0 / 2 + k2];
            float hv0 = __bfloat162float(vh.x) + __bfloat162float(vl.x);
            float hv1 = __bfloat162float(vh.y) + __bfloat162float(vl.y);
#pragma unroll
            for (int pair = 0; pair < 2; pair++) {
                float xv = pair ? hv1 : hv0;
                int k = k2 * 2 + pair;
                float4 a0 = *(const float4*)&sA[k][half * 8];
                float4 a1 = *(const float4*)&sA[k][half * 8 + 4];
                acc[0] += xv * a0.x; acc[1] += xv * a0.y;
                acc[2] += xv * a0.z; acc[3] += xv * a0.w;
                acc[4] += xv * a1.x; acc[5] += xv * a1.y;
                acc[6] += xv * a1.z; acc[7] += xv * a1.w;
            }
        }
        __syncthreads();
    }
#pragma unroll
    for (int q = 0; q < 8; q++) {
        bf16 h, l; split2(2.0f * acc[q], h, l);
        size_t o = (size_t)(row0 + row) * RR + half * 8 + q;
        g_s2h[o] = h; g_s2l[o] = l;
    }
}

// ---------------- GEMM: 128x128 CTA tile, warp 64x32, BK=32, 3-stage ---------
template<int KD, int ND, bool MLP1>
__global__ void __launch_bounds__(256) k_gemm(const float* __restrict__ bias_g) {
    extern __shared__ char smem[];
    int*   sTok  = (int*)(smem + TOK_OFF);
    float* sGate = (float*)(smem + GATE_OFF);

    int row0 = blockIdx.y * 128;
    if (row0 >= g_off[NG]) return;
    int grp = grp_of(row0);
    int e  = grp >> 2;
    int j0 = blockIdx.x * 128;
    int tid = threadIdx.x;

    if (tid < 128) {
        sTok[tid]  = g_pairTok[row0 + tid];
        sGate[tid] = g_pairGate[row0 + tid];
    }
    __syncthreads();

    const bf16* Ah = MLP1 ? g_xh  : g_hh;
    const bf16* Al = MLP1 ? g_xl  : g_hl;
    const bf16* Wh = MLP1 ? g_w1h : g_w2h;
    const bf16* Wl = MLP1 ? g_w1l : g_w2l;
    const bf16* Rh = MLP1 ? g_r1h : g_s2h;
    const bf16* Rl = MLP1 ? g_r1l : g_s2l;
    const bf16* Lh = MLP1 ? g_b1h : g_b2h;
    const bf16* Ll = MLP1 ? g_b1l : g_b2l;

    const int SM32 = KD / 32;
    const int S    = SM32 + 1;    // + LoRA (K=16) stage

    auto fill = [&](int s) {
        char* base = smem + (s % NSTG) * STAGE_B;
        bf16* dAh = (bf16*)base;
        bf16* dAl = (bf16*)(base + STG_AL);
        bf16* dBh = (bf16*)(base + STG_BH);
        bf16* dBl = (bf16*)(base + STG_BL);
        int r = tid >> 1;
        if (s < SM32) {
            int k0 = s * 32;
            size_t aoff; int sz = 16;
            if (MLP1) {
                int tok = sTok[r];
                sz = tok >= 0 ? 16 : 0;
                aoff = (size_t)(tok >= 0 ? tok : 0) * KD + k0;
            } else aoff = (size_t)(row0 + r) * KD + k0;
#pragma unroll
            for (int q = 0; q < 2; q++) {
                int c = (tid & 1) * 2 + q;        // 0..3
                cp16(dAh + r * A_ST + c * 8, Ah + aoff + c * 8, sz);
                cp16(dAl + r * A_ST + c * 8, Al + aoff + c * 8, sz);
            }
            int br = tid >> 3;                    // 0..31
            size_t woff = (size_t)e * ((size_t)KD * ND) + (size_t)(k0 + br) * ND + j0;
#pragma unroll
            for (int q = 0; q < 2; q++) {
                int c = (tid & 7) * 2 + q;        // 0..15
                cp16(dBh + br * B_ST + c * 8, Wh + woff + c * 8, 16);
                cp16(dBl + br * B_ST + c * 8, Wl + woff + c * 8, 16);
            }
        } else {
            // LoRA: A 128x16, B 16x128
            int seg = tid & 1;
            size_t roff = (size_t)(row0 + r) * RR + seg * 8;
            cp16(dAh + r * A_ST + seg * 8, Rh + roff, 16);
            cp16(dAl + r * A_ST + seg * 8, Rl + roff, 16);
            int br = tid >> 4;                    // 0..15
            int c  = tid & 15;
            size_t boff = ((size_t)grp * RR + br) * ND + j0 + c * 8;
            cp16(dBh + br * B_ST + c * 8, Lh + boff, 16);
            cp16(dBl + br * B_ST + c * 8, Ll + boff, 16);
        }
        CP_COMMIT;
    };

    const int warp = tid >> 5, lane = tid & 31;
    const int wm = (warp >> 2) * 64, wn = (warp & 3) * 32;
    const int arow = lane & 15, acol = (lane >> 4) * 8;
    const int bg = lane >> 3;
    const int brow = (bg & 1) * 8 + (lane & 7);

    float acc[4][4][4];
#pragma unroll
    for (int mt = 0; mt < 4; mt++)
#pragma unroll
        for (int nt = 0; nt < 4; nt++)
#pragma unroll
            for (int q = 0; q < 4; q++) acc[mt][nt][q] = 0.f;

    fill(0);
    if (S > 1) fill(1);

    for (int s = 0; s < S; s++) {
        if (s + 2 < S) { fill(s + 2); CP_WAIT2; }
        else if (s + 1 < S) { CP_WAIT1; }
        else { CP_WAIT0; }
        __syncthreads();

        char* base = smem + (s % NSTG) * STAGE_B;
        bf16* bAh = (bf16*)base;
        bf16* bAl = (bf16*)(base + STG_AL);
        bf16* bBh = (bf16*)(base + STG_BH);
        bf16* bBl = (bf16*)(base + STG_BL);
        int nh = (s == SM32) ? 1 : 2;

        for (int kh = 0; kh < nh; kh++) {
            unsigned ah[4][4], al[4][4], bh[4][2], bl[4][2];
#pragma unroll
            for (int mt = 0; mt < 4; mt++) {
                unsigned ad = sm_u32(bAh + (wm + mt * 16 + arow) * A_ST + kh * 16 + acol);
                LDSM_X4(ah[mt][0], ah[mt][1], ah[mt][2], ah[mt][3], ad);
                unsigned ad2 = sm_u32(bAl + (wm + mt * 16 + arow) * A_ST + kh * 16 + acol);
                LDSM_X4(al[mt][0], al[mt][1], al[mt][2], al[mt][3], ad2);
            }
#pragma unroll
            for (int np = 0; np < 2; np++) {
                int bcol = wn + (np * 2 + (bg >> 1)) * 8;
                unsigned bd = sm_u32(bBh + (kh * 16 + brow) * B_ST + bcol);
                LDSM_X4T(bh[np * 2][0], bh[np * 2][1], bh[np * 2 + 1][0], bh[np * 2 + 1][1], bd);
                unsigned bd2 = sm_u32(bBl + (kh * 16 + brow) * B_ST + bcol);
                LDSM_X4T(bl[np * 2][0], bl[np * 2][1], bl[np * 2 + 1][0], bl[np * 2 + 1][1], bd2);
            }
#pragma unroll
            for (int mt = 0; mt < 4; mt++)
#pragma unroll
                for (int nt = 0; nt < 4; nt++) MMA16816(acc[mt][nt], ah[mt], bh[nt]);
#pragma unroll
            for (int mt = 0; mt < 4; mt++)
#pragma unroll
                for (int nt = 0; nt < 4; nt++) MMA16816(acc[mt][nt], ah[mt], bl[nt]);
#pragma unroll
            for (int mt = 0; mt < 4; mt++)
#pragma unroll
                for (int nt = 0; nt < 4; nt++) MMA16816(acc[mt][nt], al[mt], bh[nt]);
        }
        __syncthreads();
    }

    // epilogue
#pragma unroll
    for (int mt = 0; mt < 4; mt++) {
#pragma unroll
        for (int nt = 0; nt < 4; nt++) {
            int c0  = wn + nt * 8 + (lane & 3) * 2;
            int col = j0 + c0;
            float bias0 = bias_g[(size_t)e * ND + col];
            float bias1 = bias_g[(size_t)e * ND + col + 1];
#pragma unroll
            for (int hf = 0; hf < 2; hf++) {
                int r = wm + mt * 16 + (lane >> 2) + hf * 8;
                float v0 = acc[mt][nt][hf * 2 + 0] + bias0;
                float v1 = acc[mt][nt][hf * 2 + 1] + bias1;
                if (MLP1) {
                    v0 = gelu_exact(v0); v1 = gelu_exact(v1);
                    bf16 h0, l0, h1, l1;
                    split2(v0, h0, l0); split2(v1, h1, l1);
                    size_t o = (size_t)(row0 + r) * ND + col;
                    *(__nv_bfloat162*)(g_hh + o) = __halves2bfloat162(h0, h1);
                    *(__nv_bfloat162*)(g_hl + o) = __halves2bfloat162(l0, l1);
                } else {
                    float gv = sGate[r];
                    size_t o = (size_t)(row0 + r) * ND + col;
                    g_yp[o]     = gv * v0;
                    g_yp[o + 1] = gv * v1;
                }
            }
        }
    }
}

// ---------------- gather: y[tok] = yp[p0] + yp[p1] ---------------------------
__global__ void k_gather(float* __restrict__ y) {
    int idx = blockIdx.x * 256 + threadIdx.x;
    if (idx >= NTOK * (OO / 4)) return;
    int tok = idx / (OO / 4);
    int c4  = idx - tok * (OO / 4);
    int p0 = g_tokP[tok * 2], p1 = g_tokP[tok * 2 + 1];
    float4 a = ((const float4*)g_yp)[(size_t)p0 * (OO / 4) + c4];
    float4 b = ((const float4*)g_yp)[(size_t)p1 * (OO / 4) + c4];
    float4 r;
    r.x = a.x + b.x; r.y = a.y + b.y; r.z = a.z + b.z; r.w = a.w + b.w;
    ((float4*)y)[idx] = r;
}

// ---------------- launch ------------------------------------------------------
extern "C" void kernel_launch(void* const* d_in, const int* in_sizes, int n_in,
                              void* d_out, int out_size) {
    const float* x    = (const float*)d_in[0];
    const int*   band = (const int*)d_in[1];
    const float* wg   = (const float*)d_in[2];
    const float* W1   = (const float*)d_in[3];
    const float* b1   = (const float*)d_in[4];
    const float* W2   = (const float*)d_in[5];
    const float* b2   = (const float*)d_in[6];
    const float* A1   = (const float*)d_in[7];
    const float* B1   = (const float*)d_in[8];
    const float* A2   = (const float*)d_in[9];
    const float* B2   = (const float*)d_in[10];
    float* out = (float*)d_out;

    cudaFuncSetAttribute(k_gemm<DD, HH, true >,
                         cudaFuncAttributeMaxDynamicSharedMemorySize, SMEM_TOTAL);
    cudaFuncSetAttribute(k_gemm<HH, OO, false>,
                         cudaFuncAttributeMaxDynamicSharedMemorySize, SMEM_TOTAL);

    k_init<<<(out_size + 255) / 256, 256>>>(out, out_size);
    k_gate<<<NTOK / 4, 128>>>(x, wg, band);
    k_loss<<<1, 256>>>(out, out_size);
    k_prep<<<(MAXP2 + 255) / 256, 256>>>();
    k_scatter<<<NTOK / 256, 256>>>(band);

    k_split_x <<<(NTOK * DD / 4 + 255) / 256, 256>>>(x);
    k_split_w1<<<(EE * DD * HH / 4 + 255) / 256, 256>>>(W1);
    k_split_w2<<<(EE * HH * OO / 4 + 255) / 256, 256>>>(W2);
    k_split_b1<<<(NG * RR * HH / 4 + 255) / 256, 256>>>(B1);
    k_split_b2<<<(NG * RR * OO / 4 + 255) / 256, 256>>>(B2);

    k_r1<<<RTMAX2, 256>>>(x, A1);
    k_gemm<DD, HH, true ><<<dim3(HH / 128, RTMAX2), 256, SMEM_TOTAL>>>(b1);
    k_s2<<<RTMAX2, 256>>>(A2);
    k_gemm<HH, OO, false><<<dim3(OO / 128, RTMAX2), 256, SMEM_TOTAL>>>(b2);
    k_gather<<<(NTOK * (OO / 4) + 255) / 256, 256>>>(out);
}